// round 3
// baseline (speedup 1.0000x reference)
#include <cuda_runtime.h>
#include <cuda_bf16.h>

// out[row, :] = W[days[row], :] + bias, D = 1024 floats = 256 float4.
// One CTA of 256 threads handles 8 rows in two pipelined batches of 4,
// keeping register pressure <=32 so 8 CTAs (64 warps) fit per SM.
static constexpr int D4 = 256;          // 1024 / 4
static constexpr int ROWS_PER_CTA = 8;
static constexpr int BATCH = 4;

__global__ void __launch_bounds__(256, 8)
doy_gather8x4_kernel(const int* __restrict__ days,
                     const float4* __restrict__ W4,
                     const float4* __restrict__ b4,
                     float4* __restrict__ out4)
{
    const int d4   = threadIdx.x;                 // column (float4 index)
    const int row0 = blockIdx.x * ROWS_PER_CTA;

    const float4 b = __ldg(b4 + d4);              // once per thread

    // All 8 index loads up front (broadcast within CTA, cheap)
    int day[ROWS_PER_CTA];
#pragma unroll
    for (int r = 0; r < ROWS_PER_CTA; ++r)
        day[r] = __ldg(days + row0 + r);

#pragma unroll
    for (int batch = 0; batch < ROWS_PER_CTA / BATCH; ++batch) {
        const int base = batch * BATCH;
        float4 w[BATCH];
#pragma unroll
        for (int r = 0; r < BATCH; ++r)
            w[r] = __ldg(W4 + (size_t)day[base + r] * D4 + d4);  // L2-resident table

#pragma unroll
        for (int r = 0; r < BATCH; ++r) {
            float4 v;
            v.x = w[r].x + b.x;
            v.y = w[r].y + b.y;
            v.z = w[r].z + b.z;
            v.w = w[r].w + b.w;
            // streaming store: 537MB write-once stream, keep it out of L2
            __stcs(out4 + (size_t)(row0 + base + r) * D4 + d4, v);
        }
    }
}

extern "C" void kernel_launch(void* const* d_in, const int* in_sizes, int n_in,
                              void* d_out, int out_size)
{
    const int*    days = (const int*)d_in[0];
    const float4* W4   = (const float4*)d_in[1];
    const float4* b4   = (const float4*)d_in[2];
    float4*       out4 = (float4*)d_out;

    const int n_rows = in_sizes[0];                 // B*T = 131072 (divisible by 8)
    const int n_cta  = n_rows / ROWS_PER_CTA;       // 16384

    doy_gather8x4_kernel<<<n_cta, 256>>>(days, W4, b4, out4);
}